// round 7
// baseline (speedup 1.0000x reference)
#include <cuda_runtime.h>
#include <cuda_bf16.h>

#define BQ  256
#define TT  512
#define EE  128
#define HH  256
#define H3  768
#define NTH 384

typedef unsigned long long u64;

// ---------------- device scratch ----------------
__device__ float g_wT[2 * 384 * H3];   // [dir][k(0..383)][j(0..767)]
__device__ float g_fc1T[512 * 128];
__device__ float g_fc2T[128 * 64];
__device__ float g_h[BQ * 2 * HH];
__device__ int   g_order[BQ];

// ---------------- helpers ----------------
__device__ __forceinline__ u64 ffma2(u64 a, u64 b, u64 c) {
    u64 d; asm("fma.rn.f32x2 %0, %1, %2, %3;" : "=l"(d) : "l"(a), "l"(b), "l"(c)); return d;
}
__device__ __forceinline__ u64 pack2(float lo, float hi) {
    u64 d; asm("mov.b64 %0, {%1, %2};" : "=l"(d) : "f"(lo), "f"(hi)); return d;
}
__device__ __forceinline__ float lo_of(u64 v) {
    float a, b; asm("mov.b64 {%0, %1}, %2;" : "=f"(a), "=f"(b) : "l"(v)); return a;
}
__device__ __forceinline__ float sigf(float x) { return __fdividef(1.0f, 1.0f + __expf(-x)); }
__device__ __forceinline__ float tanhfast(float x) { return 1.0f - __fdividef(2.0f, __expf(2.0f * x) + 1.0f); }

// ---------------- prep: transpose weights (R1-validated layout) ----------------
__global__ void prep_kernel(const float* __restrict__ wihf, const float* __restrict__ whhf,
                            const float* __restrict__ wihb, const float* __restrict__ whhb,
                            const float* __restrict__ fc1w, const float* __restrict__ fc2w) {
    int idx = blockIdx.x * blockDim.x + threadIdx.x;
    const int NW = 2 * 384 * H3;
    if (idx < NW) {
        int dir = idx / (384 * H3);
        int r   = idx % (384 * H3);
        int k = r / H3, j = r % H3;
        const float* wih = dir ? wihb : wihf;
        const float* whh = dir ? whhb : whhf;
        g_wT[idx] = (k < 128) ? wih[j * EE + k] : whh[j * HH + (k - 128)];
    } else if (idx < NW + 512 * 128) {
        int o = idx - NW; int k = o / 128, i = o % 128;
        g_fc1T[o] = fc1w[i * 512 + k];
    } else if (idx < NW + 512 * 128 + 128 * 64) {
        int o = idx - (NW + 512 * 128); int k = o / 64, i = o % 64;
        g_fc2T[o] = fc2w[i * 128 + k];
    }
}

// ---------------- sort batch by length (ascending bitonic) ----------------
__global__ void sort_kernel(const int* __restrict__ lengths) {
    __shared__ int key[BQ], val[BQ];
    unsigned t = threadIdx.x;
    key[t] = lengths[t]; val[t] = (int)t;
    __syncthreads();
    for (unsigned size = 2; size <= BQ; size <<= 1) {
        for (unsigned stride = size >> 1; stride > 0; stride >>= 1) {
            __syncthreads();
            unsigned j = t ^ stride;
            if (j > t) {
                bool up = ((t & size) == 0);
                int kt = key[t], kj = key[j];
                if ((kt > kj) == up) {
                    key[t] = kj; key[j] = kt;
                    int vt = val[t]; val[t] = val[j]; val[j] = vt;
                }
            }
        }
    }
    __syncthreads();
    g_order[t] = val[t];
}

// ---------------- GRU template: independent CTA, NB batches, S-step xp chunks ----------------
// SMEM: toks[NB][512] int | es[S][128][NB] u64(dup) | xp[S][NB][768] f32 |
//       pre[NB][768] f32 | hcur[256][NB] u64(dup) | obs[NB], lens[NB]
template<int NB, int S>
__global__ __launch_bounds__(NTH, 1) void gru_kernel(
    int rank_off,
    const int* __restrict__ x, const int* __restrict__ lengths,
    const float* __restrict__ emb,
    const float* __restrict__ bih_f, const float* __restrict__ bhh_f,
    const float* __restrict__ bih_b, const float* __restrict__ bhh_b) {

    const int grp = blockIdx.x, dir = blockIdx.y, tid = threadIdx.x;
    const int j2 = 2 * tid;                // this thread's output col pair

    extern __shared__ __align__(16) char sm[];
    int*   toks = (int*)sm;                                          // NB*512
    u64*   es   = (u64*)(sm + NB * TT * 4);                          // S*128*NB
    float* xp   = (float*)(sm + NB * TT * 4 + S * 128 * NB * 8);     // S*NB*768
    float* pre  = xp + S * NB * 768;                                 // NB*768
    u64*   hcur = (u64*)(pre + NB * 768);                            // 256*NB
    int*   obs  = (int*)(hcur + 256 * NB);
    int*   lens = obs + NB;

    if (tid < NB) {
        int o = g_order[rank_off + grp * NB + tid];
        obs[tid] = o;
        lens[tid] = lengths[o];
    }
    __syncthreads();

    // preload all tokens (coalesced) + zero hidden
    for (int i = tid; i < NB * TT; i += NTH) {
        int nb = i >> 9, t = i & (TT - 1);
        toks[i] = x[obs[nb] * TT + t];
    }
    for (int i = tid; i < 256 * NB; i += NTH) hcur[i] = 0ull;
    __syncthreads();

    const int M = lens[NB - 1];            // ascending sort -> last is max
    const float* wb  = g_wT + dir * (384 * H3);
    const float* whb = wb + 128 * H3;
    const float* bihp = dir ? bih_b : bih_f;
    const float* bhhp = dir ? bhh_b : bhh_f;
    const u64 bX = *(const u64*)(bihp + j2);   // {b_c0, b_c1}
    const u64 bH = *(const u64*)(bhhp + j2);

    const int nchunks = (M + S - 1) / S;
    for (int c = 0; c < nchunks; c++) {
        const int s0 = c * S;

        // ---- gather embeddings for steps s0..s0+S-1 (dup-pair format) ----
        for (int i = tid; i < S * NB * 32; i += NTH) {
            int ss = i / (NB * 32);
            int r  = i - ss * NB * 32;
            int nb = r >> 5, ln = r & 31;
            int sg = s0 + ss;
            int t  = dir ? (M - 1 - sg) : sg;
            t = min(max(t, 0), TT - 1);
            int tok = toks[nb * TT + t];
            float4 v = *(const float4*)(emb + (size_t)tok * EE + ln * 4);
            u64* ep = es + (size_t)(ss * 128 + ln * 4) * NB + nb;
            ep[0 * NB] = pack2(v.x, v.x);
            ep[1 * NB] = pack2(v.y, v.y);
            ep[2 * NB] = pack2(v.z, v.z);
            ep[3 * NB] = pack2(v.w, v.w);
        }
        __syncthreads();

        // ---- xp chunk: one W_ih pass computes S steps of input projections ----
        {
            u64 acc[S][NB];
#pragma unroll
            for (int ss = 0; ss < S; ss++)
#pragma unroll
                for (int nb = 0; nb < NB; nb++) acc[ss][nb] = bX;
#pragma unroll 4
            for (int k = 0; k < 128; k++) {
                u64 wv = *(const u64*)(wb + k * H3 + j2);   // {w[k][c0], w[k][c1]}
#pragma unroll
                for (int ss = 0; ss < S; ss++) {
#pragma unroll
                    for (int np = 0; np < NB; np += 2) {
                        ulonglong2 e2 = *(const ulonglong2*)(es + (size_t)(ss * 128 + k) * NB + np);
                        acc[ss][np]     = ffma2(wv, e2.x, acc[ss][np]);
                        acc[ss][np + 1] = ffma2(wv, e2.y, acc[ss][np + 1]);
                    }
                }
            }
#pragma unroll
            for (int ss = 0; ss < S; ss++)
#pragma unroll
                for (int nb = 0; nb < NB; nb++)
                    *(u64*)(xp + (size_t)(ss * NB + nb) * H3 + j2) = acc[ss][nb];
        }

        // ---- per-step recurrence within chunk ----
        for (int ss = 0; ss < S; ss++) {
            const int s = s0 + ss;
            if (s >= M) break;

            // hidden projection: W_hh pass
            {
                u64 hacc[NB];
#pragma unroll
                for (int nb = 0; nb < NB; nb++) hacc[nb] = bH;
#pragma unroll 8
                for (int k = 0; k < 256; k++) {
                    u64 wv = *(const u64*)(whb + k * H3 + j2);
#pragma unroll
                    for (int np = 0; np < NB; np += 2) {
                        ulonglong2 h2 = *(const ulonglong2*)(hcur + (size_t)k * NB + np);
                        hacc[np]     = ffma2(wv, h2.x, hacc[np]);
                        hacc[np + 1] = ffma2(wv, h2.y, hacc[np + 1]);
                    }
                }
#pragma unroll
                for (int nb = 0; nb < NB; nb++)
                    *(u64*)(pre + (size_t)nb * H3 + j2) = hacc[nb];
            }
            __syncthreads();

            // gates + ragged mask + hidden update
            {
                const int t = dir ? (M - 1 - s) : s;
                for (int i = tid; i < 256 * NB; i += NTH) {
                    int u = i & 255, nb = i >> 8;
                    const float* xr_p = xp + (size_t)(ss * NB + nb) * H3;
                    const float* hr_p = pre + (size_t)nb * H3;
                    float r  = sigf(xr_p[u] + hr_p[u]);
                    float z  = sigf(xr_p[256 + u] + hr_p[256 + u]);
                    float nv = tanhfast(xr_p[512 + u] + r * hr_p[512 + u]);
                    float hold = lo_of(hcur[(size_t)u * NB + nb]);
                    float hnew = (t < lens[nb]) ? ((1.0f - z) * nv + z * hold) : hold;
                    hcur[(size_t)u * NB + nb] = pack2(hnew, hnew);
                }
            }
            __syncthreads();
        }
    }

    // final hidden -> g_h
    for (int i = tid; i < 256 * NB; i += NTH) {
        int u = i & 255, nb = i >> 8;
        g_h[(size_t)obs[nb] * (2 * HH) + dir * HH + u] = lo_of(hcur[(size_t)u * NB + nb]);
    }
}

// ---------------- head: fc1 + relu + fc2 + L2 normalize ----------------
__global__ __launch_bounds__(128) void head_kernel(const float* __restrict__ fc1_b,
                                                   const float* __restrict__ fc2_b,
                                                   float* __restrict__ out) {
    __shared__ float hsm[512];
    __shared__ float hid[128];
    __shared__ float osm[64];
    __shared__ float inv_s;
    const int b = blockIdx.x, t = threadIdx.x;

    ((float4*)hsm)[t] = ((const float4*)(g_h + (size_t)b * 512))[t];
    __syncthreads();

    float acc = fc1_b[t];
#pragma unroll 8
    for (int k = 0; k < 512; k++) acc += g_fc1T[k * 128 + t] * hsm[k];
    hid[t] = fmaxf(acc, 0.0f);
    __syncthreads();

    if (t < 64) {
        float a = fc2_b[t];
#pragma unroll 8
        for (int k = 0; k < 128; k++) a += g_fc2T[k * 64 + t] * hid[k];
        osm[t] = a;
    }
    __syncthreads();
    if (t == 0) {
        float ss = 0.0f;
        for (int o = 0; o < 64; o++) ss += osm[o] * osm[o];
        inv_s = 1.0f / fmaxf(sqrtf(ss), 1e-12f);
    }
    __syncthreads();
    if (t < 64) out[b * 64 + t] = osm[t] * inv_s;
}

// ---------------- launch ----------------
static constexpr int smem_bytes(int NBv, int Sv) {
    return NBv * TT * 4            // toks
         + Sv * 128 * NBv * 8      // es (dup u64)
         + Sv * NBv * 768 * 4      // xp
         + NBv * 768 * 4           // pre
         + 256 * NBv * 8           // hcur (dup u64)
         + 2 * NBv * 4 + 16;       // obs, lens
}

extern "C" void kernel_launch(void* const* d_in, const int* in_sizes, int n_in,
                              void* d_out, int out_size) {
    const int*   x        = (const int*)d_in[0];
    const int*   lengths  = (const int*)d_in[1];
    const float* emb      = (const float*)d_in[2];
    const float* w_ih_f   = (const float*)d_in[3];
    const float* w_hh_f   = (const float*)d_in[4];
    const float* b_ih_f   = (const float*)d_in[5];
    const float* b_hh_f   = (const float*)d_in[6];
    const float* w_ih_b   = (const float*)d_in[7];
    const float* w_hh_b   = (const float*)d_in[8];
    const float* b_ih_b   = (const float*)d_in[9];
    const float* b_hh_b   = (const float*)d_in[10];
    const float* fc1_w    = (const float*)d_in[11];
    const float* fc1_b    = (const float*)d_in[12];
    const float* fc2_w    = (const float*)d_in[13];
    const float* fc2_b    = (const float*)d_in[14];
    float* out = (float*)d_out;

    static bool attr_set = false;
    if (!attr_set) {
        cudaFuncSetAttribute(gru_kernel<16, 1>, cudaFuncAttributeMaxDynamicSharedMemorySize, smem_bytes(16, 1));
        cudaFuncSetAttribute(gru_kernel<8, 2>,  cudaFuncAttributeMaxDynamicSharedMemorySize, smem_bytes(8, 2));
        cudaFuncSetAttribute(gru_kernel<4, 4>,  cudaFuncAttributeMaxDynamicSharedMemorySize, smem_bytes(4, 4));
        attr_set = true;
    }

    const int total = 2 * 384 * H3 + 512 * 128 + 128 * 64;
    prep_kernel<<<(total + 255) / 256, 256>>>(w_ih_f, w_hh_f, w_ih_b, w_hh_b, fc1_w, fc2_w);
    sort_kernel<<<1, BQ>>>(lengths);
    sort_kernel<<<1, BQ>>>(lengths);   // dummy re-run: positions gru<4,4> at launch #6 for ncu -s 5 -c 1

    // class launches: ranks [0,64) NB=16 | [64,176) NB=8 | [176,256) NB=4
    gru_kernel<16, 1><<<dim3(4, 2),  NTH, smem_bytes(16, 1)>>>(0,   x, lengths, emb, b_ih_f, b_hh_f, b_ih_b, b_hh_b);
    gru_kernel<8, 2><<<dim3(14, 2),  NTH, smem_bytes(8, 2)>>>(64,  x, lengths, emb, b_ih_f, b_hh_f, b_ih_b, b_hh_b);
    gru_kernel<4, 4><<<dim3(20, 2),  NTH, smem_bytes(4, 4)>>>(176, x, lengths, emb, b_ih_f, b_hh_f, b_ih_b, b_hh_b);

    head_kernel<<<BQ, 128>>>(fc1_b, fc2_b, out);
}

// round 9
// speedup vs baseline: 2.0249x; 2.0249x over previous
#include <cuda_runtime.h>
#include <cuda_bf16.h>

#define BQ   256
#define TT   512
#define EE   128
#define HH   256
#define NB   32      // batches per group (cluster)
#define NGRP 8       // groups per direction
#define NCTA 8       // cluster size (j-split)
#define ROWS 96      // gate rows per CTA
#define NTH  384
#define XH_BYTES (HH * NB * 4)   // 32768

typedef unsigned long long u64;

// ---------------- device scratch ----------------
__device__ float g_wt[2 * NCTA * 384 * ROWS];   // [dir][cta][k][row]
__device__ float g_fc1T[512 * 128];
__device__ float g_fc2T[128 * 64];
__device__ float g_h[BQ * 2 * HH];
__device__ int   g_order[BQ];

// ---------------- math helpers ----------------
__device__ __forceinline__ u64 ffma2(u64 a, u64 b, u64 c) {
    u64 d; asm("fma.rn.f32x2 %0, %1, %2, %3;" : "=l"(d) : "l"(a), "l"(b), "l"(c)); return d;
}
__device__ __forceinline__ u64 pack2(float lo, float hi) {
    u64 d; asm("mov.b64 %0, {%1, %2};" : "=l"(d) : "f"(lo), "f"(hi)); return d;
}
__device__ __forceinline__ float sigf(float x) { return __fdividef(1.0f, 1.0f + __expf(-x)); }
__device__ __forceinline__ float tanhfast(float x) { return 1.0f - __fdividef(2.0f, __expf(2.0f * x) + 1.0f); }

// ---------------- cluster / mbarrier helpers ----------------
__device__ __forceinline__ unsigned smem_u32(const void* p) {
    unsigned a;
    asm("{ .reg .u64 t; cvta.to.shared.u64 t, %1; cvt.u32.u64 %0, t; }" : "=r"(a) : "l"(p));
    return a;
}
__device__ __forceinline__ unsigned mapa_sm(unsigned addr, unsigned rank) {
    unsigned r; asm("mapa.shared::cluster.u32 %0, %1, %2;" : "=r"(r) : "r"(addr), "r"(rank));
    return r;
}
__device__ __forceinline__ void mbar_init(unsigned a, unsigned c) {
    asm volatile("mbarrier.init.shared.b64 [%0], %1;" :: "r"(a), "r"(c) : "memory");
}
__device__ __forceinline__ void mbar_arrive_expect_tx(unsigned a, unsigned tx) {
    asm volatile("mbarrier.arrive.expect_tx.shared.b64 _, [%0], %1;" :: "r"(a), "r"(tx) : "memory");
}
__device__ __forceinline__ void mbar_arrive_remote(unsigned a) {
    asm volatile("mbarrier.arrive.release.cluster.shared::cluster.b64 _, [%0];" :: "r"(a) : "memory");
}
__device__ __forceinline__ void mbar_wait_par(unsigned addr, unsigned par) {
    asm volatile(
        "{\n\t.reg .pred P;\n\t"
        "WAITLOOP_%=:\n\t"
        "mbarrier.try_wait.parity.acquire.cluster.shared::cta.b64 P, [%0], %1, 0x989680;\n\t"
        "@P bra.uni WAITDONE_%=;\n\t"
        "bra.uni WAITLOOP_%=;\n\t"
        "WAITDONE_%=:\n\t}"
        :: "r"(addr), "r"(par) : "memory");
}
__device__ __forceinline__ void st_async_u64(unsigned dst, u64 v, unsigned mbar) {
    asm volatile("st.async.shared::cluster.mbarrier::complete_tx::bytes.b64 [%0], %1, [%2];"
                 :: "r"(dst), "l"(v), "r"(mbar) : "memory");
}
#define CLUSTER_SYNC() do { \
    asm volatile("barrier.cluster.arrive.aligned;" ::: "memory"); \
    asm volatile("barrier.cluster.wait.aligned;"   ::: "memory"); \
} while (0)

// SMEM layout (bytes)
#define OFF_WT   0          // [384][96] f32 : 147456
#define OFF_EMB  147456     // [128][32] f32 : 16384
#define OFF_XH   163840     // [256][32] f32 : 32768
#define OFF_PX   196608     // [96][32]  f32 : 12288
#define OFF_PH   208896     // [96][32]  f32 : 12288
#define OFF_OB   221184     // int[32]
#define OFF_LEN  221312     // int[32]
#define OFF_MBF  221440     // u64
#define OFF_MBE  221456     // u64
#define SMEM_SZ  221696

// ---------------- prep ----------------
__global__ void prep_kernel(const float* __restrict__ wihf, const float* __restrict__ whhf,
                            const float* __restrict__ wihb, const float* __restrict__ whhb,
                            const float* __restrict__ fc1w, const float* __restrict__ fc2w) {
    int idx = blockIdx.x * blockDim.x + threadIdx.x;
    const int NW = 2 * NCTA * 384 * ROWS;            // 589824
    const int B1 = NW, B2 = B1 + 512 * 128, B3 = B2 + 128 * 64;
    if (idx < NW) {
        int r   = idx % ROWS;
        int k   = (idx / ROWS) % 384;
        int cta = (idx / (ROWS * 384)) % NCTA;
        int dir = idx / (ROWS * 384 * NCTA);
        const float* wih = dir ? wihb : wihf;
        const float* whh = dir ? whhb : whhf;
        int grow = (r >> 5) * HH + cta * 32 + (r & 31);   // gate*256 + col
        g_wt[idx] = (k < 128) ? wih[grow * EE + k] : whh[grow * HH + (k - 128)];
    } else if (idx < B2) {
        int o = idx - B1; int k = o / 128, i = o % 128;
        g_fc1T[o] = fc1w[i * 512 + k];
    } else if (idx < B3) {
        int o = idx - B2; int k = o / 64, i = o % 64;
        g_fc2T[o] = fc2w[i * 128 + k];
    }
}

// ---------------- sort batch by length (ascending bitonic) ----------------
__global__ void sort_kernel(const int* __restrict__ lengths) {
    __shared__ int key[BQ], val[BQ];
    unsigned t = threadIdx.x;
    key[t] = lengths[t]; val[t] = (int)t;
    __syncthreads();
    for (unsigned size = 2; size <= BQ; size <<= 1) {
        for (unsigned stride = size >> 1; stride > 0; stride >>= 1) {
            __syncthreads();
            unsigned j = t ^ stride;
            if (j > t) {
                bool up = ((t & size) == 0);
                int kt = key[t], kj = key[j];
                if ((kt > kj) == up) {
                    key[t] = kj; key[j] = kt;
                    int vt = val[t]; val[t] = val[j]; val[j] = vt;
                }
            }
        }
    }
    __syncthreads();
    g_order[t] = val[t];
}

// ---------------- GRU: 8-CTA cluster, SMEM weights, st.async h-exchange ----------------
__global__ __launch_bounds__(NTH, 1) __cluster_dims__(NCTA, 1, 1)
void gru_kernel(const int* __restrict__ x, const int* __restrict__ lengths,
                const float* __restrict__ emb,
                const float* __restrict__ bih_f, const float* __restrict__ bhh_f,
                const float* __restrict__ bih_b, const float* __restrict__ bhh_b) {

    const int cta = blockIdx.x, grp = blockIdx.y, dir = blockIdx.z;
    const int tid = threadIdx.x;
    const int rp  = tid >> 3;          // row-pair 0..47
    const int bq4 = (tid & 7) * 4;     // batch base 0..28

    extern __shared__ __align__(16) char sm[];
    float* wt   = (float*)(sm + OFF_WT);
    float* embb = (float*)(sm + OFF_EMB);
    float* xh   = (float*)(sm + OFF_XH);
    float* preX = (float*)(sm + OFF_PX);
    float* preH = (float*)(sm + OFF_PH);
    int*   obs  = (int*)(sm + OFF_OB);
    int*   lens = (int*)(sm + OFF_LEN);

    const unsigned base  = smem_u32(sm);
    const unsigned mbF_l = base + OFF_MBF;
    const unsigned mbE_l = base + OFF_MBE;

    if (tid < NB) {
        int o = g_order[grp * NB + tid];
        obs[tid] = o;
        lens[tid] = lengths[o];
    }
    // weights -> SMEM (one-time)
    {
        const float4* wg = (const float4*)(g_wt + (size_t)(dir * NCTA + cta) * 384 * ROWS);
        float4* wd = (float4*)wt;
        for (int i = tid; i < 384 * ROWS / 4; i += NTH) wd[i] = wg[i];
    }
    for (int i = tid; i < HH * NB; i += NTH) xh[i] = 0.0f;
    if (tid == 0) {
        mbar_init(mbF_l, 1);
        mbar_init(mbE_l, NCTA);
    }
    __syncthreads();
    // arm mbF phase 0 (receives h^1) BEFORE any peer can possibly store
    if (tid == 0) mbar_arrive_expect_tx(mbF_l, XH_BYTES);
    __syncthreads();
    CLUSTER_SYNC();   // mbarriers + xh zeros visible cluster-wide

    const int M = lens[NB - 1];
    const int r0 = 2 * rp, r1 = r0 + 1;
    const int grow0 = ((r0 >> 5) << 8) + cta * 32 + (r0 & 31);
    const int grow1 = ((r1 >> 5) << 8) + cta * 32 + (r1 & 31);
    const float* bihp = dir ? bih_b : bih_f;
    const float* bhhp = dir ? bhh_b : bhh_f;
    const u64 bX0 = pack2(bihp[grow0], bihp[grow0]);
    const u64 bX1 = pack2(bihp[grow1], bihp[grow1]);
    const u64 bH0 = pack2(bhhp[grow0], bhhp[grow0]);
    const u64 bH1 = pack2(bhhp[grow1], bhhp[grow1]);
    const float* wr = wt + 2 * rp;

    // E-phase addressing (tid < 256): own h slice element -> all peers
    const int ecol = tid >> 3;                 // 0..31
    const int eb4  = (tid & 7) * 4;            // 0..28
    unsigned dstA[NCTA], mbFp[NCTA], mbEp[NCTA];
    {
        unsigned woff = (unsigned)(((cta * 32 + ecol) * 32 + eb4) * 4);
#pragma unroll
        for (int p = 0; p < NCTA; p++) {
            dstA[p] = mapa_sm(base + OFF_XH, p) + woff;
            mbFp[p] = mapa_sm(mbF_l, p);
            mbEp[p] = mapa_sm(mbE_l, p);
        }
    }

    // initial embedding gather (step 0)
    {
        int t0 = dir ? (M - 1) : 0;
        for (int i = tid; i < 1024; i += NTH) {
            int nb = i & 31, k4 = i >> 5;
            int tok = x[obs[nb] * TT + t0];
            float4 v = *(const float4*)(emb + (size_t)tok * EE + k4 * 4);
            embb[(k4 * 4 + 0) * 32 + nb] = v.x;
            embb[(k4 * 4 + 1) * 32 + nb] = v.y;
            embb[(k4 * 4 + 2) * 32 + nb] = v.z;
            embb[(k4 * 4 + 3) * 32 + nb] = v.w;
        }
    }
    __syncthreads();

    unsigned pf = 0, pe = 0;

    for (int s = 0; s < M; s++) {
        // ---- A: input projection k=0..127 (independent of peers -> hides skew) ----
        {
            u64 a00 = bX0, a01 = bX0, a10 = bX1, a11 = bX1;
#pragma unroll 4
            for (int k = 0; k < 128; k++) {
                float2 w = *(const float2*)(wr + k * ROWS);
                ulonglong2 a = *(const ulonglong2*)(embb + k * 32 + bq4);
                u64 w0 = pack2(w.x, w.x), w1 = pack2(w.y, w.y);
                a00 = ffma2(w0, a.x, a00); a01 = ffma2(w0, a.y, a01);
                a10 = ffma2(w1, a.x, a10); a11 = ffma2(w1, a.y, a11);
            }
            *(ulonglong2*)(preX + r0 * 32 + bq4) = make_ulonglong2(a00, a01);
            *(ulonglong2*)(preX + r1 * 32 + bq4) = make_ulonglong2(a10, a11);
        }

        // ---- wait for h^s; re-arm full barrier for h^{s+1} ----
        if (s > 0) {
            mbar_wait_par(mbF_l, pf);
            pf ^= 1;
            if (tid == 0 && s + 1 < M) mbar_arrive_expect_tx(mbF_l, XH_BYTES);
        }

        // ---- D: hidden projection k=128..383 over xh ----
        {
            u64 a00 = bH0, a01 = bH0, a10 = bH1, a11 = bH1;
            const float* wh = wr + 128 * ROWS;
#pragma unroll 4
            for (int k = 0; k < 256; k++) {
                float2 w = *(const float2*)(wh + k * ROWS);
                ulonglong2 a = *(const ulonglong2*)(xh + k * 32 + bq4);
                u64 w0 = pack2(w.x, w.x), w1 = pack2(w.y, w.y);
                a00 = ffma2(w0, a.x, a00); a01 = ffma2(w0, a.y, a01);
                a10 = ffma2(w1, a.x, a10); a11 = ffma2(w1, a.y, a11);
            }
            *(ulonglong2*)(preH + r0 * 32 + bq4) = make_ulonglong2(a00, a01);
            *(ulonglong2*)(preH + r1 * 32 + bq4) = make_ulonglong2(a10, a11);
        }
        __syncthreads();   // all xh reads + preX/preH writes complete

        // signal "done reading h^s" to every CTA (enables their h^{s+1} stores)
        if (tid == 0 && s + 1 < M) {
#pragma unroll
            for (int p = 0; p < NCTA; p++) mbar_arrive_remote(mbEp[p]);
        }

        // ---- E: gates + combine + publish  |  warps 8-11: prefetch next embedding ----
        if (tid < 256) {
            const int tcur = dir ? (M - 1 - s) : s;
            float hv[4];
            {
                const float* pxr = preX + ecol * 32 + eb4;
                const float* phr = preH + ecol * 32 + eb4;
                const float* pxz = preX + (32 + ecol) * 32 + eb4;
                const float* phz = preH + (32 + ecol) * 32 + eb4;
                const float* pxn = preX + (64 + ecol) * 32 + eb4;
                const float* phn = preH + (64 + ecol) * 32 + eb4;
                const float* hop = xh + (cta * 32 + ecol) * 32 + eb4;
#pragma unroll
                for (int j = 0; j < 4; j++) {
                    float r  = sigf(pxr[j] + phr[j]);
                    float z  = sigf(pxz[j] + phz[j]);
                    float nv = tanhfast(pxn[j] + r * phn[j]);
                    hv[j] = (tcur < lens[eb4 + j]) ? ((1.0f - z) * nv + z * hop[j]) : hop[j];
                }
            }
            if (s + 1 < M) {
                mbar_wait_par(mbE_l, pe);    // all CTAs done reading h^s
                u64 lo = pack2(hv[0], hv[1]);
                u64 hi = pack2(hv[2], hv[3]);
#pragma unroll
                for (int p = 0; p < NCTA; p++) {
                    st_async_u64(dstA[p], lo, mbFp[p]);
                    st_async_u64(dstA[p] + 8, hi, mbFp[p]);
                }
            } else {
#pragma unroll
                for (int j = 0; j < 4; j++)
                    g_h[(size_t)obs[eb4 + j] * (2 * HH) + dir * HH + cta * 32 + ecol] = hv[j];
            }
        } else if (s + 1 < M) {
            int tn = dir ? (M - 2 - s) : (s + 1);
            for (int i = tid - 256; i < 1024; i += 128) {
                int nb = i & 31, k4 = i >> 5;
                int tok = x[obs[nb] * TT + tn];
                float4 v = *(const float4*)(emb + (size_t)tok * EE + k4 * 4);
                embb[(k4 * 4 + 0) * 32 + nb] = v.x;
                embb[(k4 * 4 + 1) * 32 + nb] = v.y;
                embb[(k4 * 4 + 2) * 32 + nb] = v.z;
                embb[(k4 * 4 + 3) * 32 + nb] = v.w;
            }
        }
        if (s + 1 < M) pe ^= 1;
        __syncthreads();
    }

    CLUSTER_SYNC();   // no CTA exits while peers' st.async may target it
}

// ---------------- head: fc1 + relu + fc2 + L2 normalize ----------------
__global__ __launch_bounds__(128) void head_kernel(const float* __restrict__ fc1_b,
                                                   const float* __restrict__ fc2_b,
                                                   float* __restrict__ out) {
    __shared__ float hsm[512];
    __shared__ float hid[128];
    __shared__ float osm[64];
    __shared__ float inv_s;
    const int b = blockIdx.x, t = threadIdx.x;

    ((float4*)hsm)[t] = ((const float4*)(g_h + (size_t)b * 512))[t];
    __syncthreads();

    float acc = fc1_b[t];
#pragma unroll 8
    for (int k = 0; k < 512; k++) acc += g_fc1T[k * 128 + t] * hsm[k];
    hid[t] = fmaxf(acc, 0.0f);
    __syncthreads();

    if (t < 64) {
        float a = fc2_b[t];
#pragma unroll 8
        for (int k = 0; k < 128; k++) a += g_fc2T[k * 64 + t] * hid[k];
        osm[t] = a;
    }
    __syncthreads();
    if (t == 0) {
        float ss = 0.0f;
        for (int o = 0; o < 64; o++) ss += osm[o] * osm[o];
        inv_s = 1.0f / fmaxf(sqrtf(ss), 1e-12f);
    }
    __syncthreads();
    if (t < 64) out[b * 64 + t] = osm[t] * inv_s;
}

// ---------------- launch ----------------
extern "C" void kernel_launch(void* const* d_in, const int* in_sizes, int n_in,
                              void* d_out, int out_size) {
    const int*   x        = (const int*)d_in[0];
    const int*   lengths  = (const int*)d_in[1];
    const float* emb      = (const float*)d_in[2];
    const float* w_ih_f   = (const float*)d_in[3];
    const float* w_hh_f   = (const float*)d_in[4];
    const float* b_ih_f   = (const float*)d_in[5];
    const float* b_hh_f   = (const float*)d_in[6];
    const float* w_ih_b   = (const float*)d_in[7];
    const float* w_hh_b   = (const float*)d_in[8];
    const float* b_ih_b   = (const float*)d_in[9];
    const float* b_hh_b   = (const float*)d_in[10];
    const float* fc1_w    = (const float*)d_in[11];
    const float* fc1_b    = (const float*)d_in[12];
    const float* fc2_w    = (const float*)d_in[13];
    const float* fc2_b    = (const float*)d_in[14];
    float* out = (float*)d_out;

    static bool attr_set = false;
    if (!attr_set) {
        cudaFuncSetAttribute(gru_kernel, cudaFuncAttributeMaxDynamicSharedMemorySize, SMEM_SZ);
        attr_set = true;
    }

    const int total = 2 * NCTA * 384 * ROWS + 512 * 128 + 128 * 64;
    prep_kernel<<<(total + 255) / 256, 256>>>(w_ih_f, w_hh_f, w_ih_b, w_hh_b, fc1_w, fc2_w);
    sort_kernel<<<1, BQ>>>(lengths);
    sort_kernel<<<1, BQ>>>(lengths);   // dummy: makes gru the 4th launch so ncu captures it
    dim3 gg(NCTA, NGRP, 2);
    gru_kernel<<<gg, NTH, SMEM_SZ>>>(x, lengths, emb, b_ih_f, b_hh_f, b_ih_b, b_hh_b);
    head_kernel<<<BQ, 128>>>(fc1_b, fc2_b, out);
}

// round 10
// speedup vs baseline: 2.4253x; 1.1977x over previous
#include <cuda_runtime.h>
#include <cuda_bf16.h>

#define BQ   256
#define TT   512
#define EE   128
#define HH   256
#define NB   32      // batches per group (cluster)
#define NGRP 8       // groups per direction
#define NCTA 8       // cluster size (j-split)
#define ROWS 96      // gate rows per CTA
#define NTH  384
#define KPAD 388     // weight row pitch (floats)
#define PXP  33      // preact row pitch (floats)
#define XH_BYTES 32768

typedef unsigned long long u64;

// ---------------- device scratch ----------------
__device__ float g_wt[2 * NCTA * ROWS * KPAD];  // [dir][cta][row][kpad]
__device__ float g_fc1T[512 * 128];
__device__ float g_fc2T[128 * 64];
__device__ float g_h[BQ * 2 * HH];
__device__ int   g_order[BQ];

// ---------------- math helpers ----------------
__device__ __forceinline__ u64 ffma2(u64 a, u64 b, u64 c) {
    u64 d; asm("fma.rn.f32x2 %0, %1, %2, %3;" : "=l"(d) : "l"(a), "l"(b), "l"(c)); return d;
}
__device__ __forceinline__ u64 pack2(float lo, float hi) {
    u64 d; asm("mov.b64 %0, {%1, %2};" : "=l"(d) : "f"(lo), "f"(hi)); return d;
}
__device__ __forceinline__ void unpack2(u64 v, float& lo, float& hi) {
    asm("mov.b64 {%0, %1}, %2;" : "=f"(lo), "=f"(hi) : "l"(v));
}
__device__ __forceinline__ float sigf(float x) { return __fdividef(1.0f, 1.0f + __expf(-x)); }
__device__ __forceinline__ float tanhfast(float x) { return 1.0f - __fdividef(2.0f, __expf(2.0f * x) + 1.0f); }

// ---------------- cluster / mbarrier helpers ----------------
__device__ __forceinline__ unsigned smem_u32(const void* p) {
    unsigned a;
    asm("{ .reg .u64 t; cvta.to.shared.u64 t, %1; cvt.u32.u64 %0, t; }" : "=r"(a) : "l"(p));
    return a;
}
__device__ __forceinline__ unsigned mapa_sm(unsigned addr, unsigned rank) {
    unsigned r; asm("mapa.shared::cluster.u32 %0, %1, %2;" : "=r"(r) : "r"(addr), "r"(rank));
    return r;
}
__device__ __forceinline__ void mbar_init(unsigned a, unsigned c) {
    asm volatile("mbarrier.init.shared.b64 [%0], %1;" :: "r"(a), "r"(c) : "memory");
}
__device__ __forceinline__ void mbar_arrive_expect_tx(unsigned a, unsigned tx) {
    asm volatile("mbarrier.arrive.expect_tx.shared.b64 _, [%0], %1;" :: "r"(a), "r"(tx) : "memory");
}
__device__ __forceinline__ void mbar_arrive_remote(unsigned a) {
    asm volatile("mbarrier.arrive.release.cluster.shared::cluster.b64 _, [%0];" :: "r"(a) : "memory");
}
__device__ __forceinline__ void mbar_wait_par(unsigned addr, unsigned par) {
    asm volatile(
        "{\n\t.reg .pred P;\n\t"
        "WAITLOOP_%=:\n\t"
        "mbarrier.try_wait.parity.acquire.cluster.shared::cta.b64 P, [%0], %1, 0x989680;\n\t"
        "@P bra.uni WAITDONE_%=;\n\t"
        "bra.uni WAITLOOP_%=;\n\t"
        "WAITDONE_%=:\n\t}"
        :: "r"(addr), "r"(par) : "memory");
}
__device__ __forceinline__ void bulk_dsmem(unsigned dst, unsigned src, unsigned bytes, unsigned mbar) {
    asm volatile("cp.async.bulk.shared::cluster.shared::cta.mbarrier::complete_tx::bytes [%0], [%1], %2, [%3];"
                 :: "r"(dst), "r"(src), "r"(bytes), "r"(mbar) : "memory");
}
#define CLUSTER_SYNC() do { \
    asm volatile("barrier.cluster.arrive.aligned;" ::: "memory"); \
    asm volatile("barrier.cluster.wait.aligned;"   ::: "memory"); \
} while (0)

// SMEM layout (bytes)
#define OFF_W    0          // [96][388] f32      : 148992
#define OFF_EMB  148992     // [32 nb][128 k] f32 : 16384  (swizzled)
#define OFF_XH   165376     // [8 sl][32 nb][32]  : 32768  (swizzled)
#define OFF_PX   198144     // [96][33] f32       : 12672
#define OFF_PH   210816     // [96][33] f32       : 12672
#define OFF_HST  223488     // 2 x 4096 staging   : 8192
#define OFF_OB   231680     // int[32]
#define OFF_LEN  231808     // int[32]
#define OFF_MBF  231936     // u64
#define OFF_MBE  231944     // u64
#define SMEM_SZ  231952

// ---------------- prep ----------------
__global__ void prep_kernel(const float* __restrict__ wihf, const float* __restrict__ whhf,
                            const float* __restrict__ wihb, const float* __restrict__ whhb,
                            const float* __restrict__ fc1w, const float* __restrict__ fc2w) {
    int idx = blockIdx.x * blockDim.x + threadIdx.x;
    const int NW = 2 * NCTA * ROWS * KPAD;           // 595968
    const int B1 = NW, B2 = B1 + 512 * 128, B3 = B2 + 128 * 64;
    if (idx < NW) {
        int k    = idx % KPAD;
        int r    = (idx / KPAD) % ROWS;
        int cta  = (idx / (KPAD * ROWS)) % NCTA;
        int dir  = idx / (KPAD * ROWS * NCTA);
        const float* wih = dir ? wihb : wihf;
        const float* whh = dir ? whhb : whhf;
        int grow = (r >> 5) * HH + cta * 32 + (r & 31);   // gate*256 + col
        float v = 0.0f;
        if (k < 128)      v = wih[grow * EE + k];
        else if (k < 384) v = whh[grow * HH + (k - 128)];
        g_wt[idx] = v;
    } else if (idx < B2) {
        int o = idx - B1; int k = o / 128, i = o % 128;
        g_fc1T[o] = fc1w[i * 512 + k];
    } else if (idx < B3) {
        int o = idx - B2; int k = o / 64, i = o % 64;
        g_fc2T[o] = fc2w[i * 128 + k];
    }
}

// ---------------- sort batch by length (ascending bitonic) ----------------
__global__ void sort_kernel(const int* __restrict__ lengths) {
    __shared__ int key[BQ], val[BQ];
    unsigned t = threadIdx.x;
    key[t] = lengths[t]; val[t] = (int)t;
    __syncthreads();
    for (unsigned size = 2; size <= BQ; size <<= 1) {
        for (unsigned stride = size >> 1; stride > 0; stride >>= 1) {
            __syncthreads();
            unsigned j = t ^ stride;
            if (j > t) {
                bool up = ((t & size) == 0);
                int kt = key[t], kj = key[j];
                if ((kt > kj) == up) {
                    key[t] = kj; key[j] = kt;
                    int vt = val[t]; val[t] = val[j]; val[j] = vt;
                }
            }
        }
    }
    __syncthreads();
    g_order[t] = val[t];
}

// ---------------- GRU: 8-CTA cluster, k-pair f32x2, bulk DSMEM exchange ----------------
__global__ __launch_bounds__(NTH, 1) __cluster_dims__(NCTA, 1, 1)
void gru_kernel(const int* __restrict__ x, const int* __restrict__ lengths,
                const float* __restrict__ emb,
                const float* __restrict__ bih_f, const float* __restrict__ bhh_f,
                const float* __restrict__ bih_b, const float* __restrict__ bhh_b) {

    const int cta = blockIdx.x, grp = blockIdx.y, dir = blockIdx.z;
    const int tid = threadIdx.x;
    const int r2  = tid >> 3;        // 0..47 (row pair)
    const int q   = tid & 7;         // nb quad index
    const int r0  = 2 * r2, r1 = r0 + 1;
    const int nb0 = 4 * q;
    const int sw  = 4 * q;           // swizzle constant: 4*((nb>>2)&7), same for all 4 owned nb

    extern __shared__ __align__(16) char sm[];
    float* w_s    = (float*)(sm + OFF_W);
    float* embs   = (float*)(sm + OFF_EMB);
    float* xh     = (float*)(sm + OFF_XH);
    float* preX   = (float*)(sm + OFF_PX);
    float* preH   = (float*)(sm + OFF_PH);
    float* hstage = (float*)(sm + OFF_HST);
    int*   obs    = (int*)(sm + OFF_OB);
    int*   lens   = (int*)(sm + OFF_LEN);

    const unsigned base  = smem_u32(sm);
    const unsigned mbF_l = base + OFF_MBF;
    const unsigned mbE_l = base + OFF_MBE;

    if (tid < NB) {
        int o = g_order[grp * NB + tid];
        obs[tid] = o;
        lens[tid] = lengths[o];
    }
    // weights -> SMEM (96*388 = 37248 floats = 9312 float4)
    {
        const float4* wg = (const float4*)(g_wt + (size_t)(dir * NCTA + cta) * ROWS * KPAD);
        float4* wd = (float4*)w_s;
        for (int i = tid; i < ROWS * KPAD / 4; i += NTH) wd[i] = wg[i];
    }
    for (int i = tid; i < XH_BYTES / 4; i += NTH) xh[i] = 0.0f;
    if (tid == 0) { mbar_init(mbF_l, 1); mbar_init(mbE_l, NCTA); }
    __syncthreads();
    if (tid == 0) mbar_arrive_expect_tx(mbF_l, XH_BYTES);   // arm for h^1 BEFORE any peer can send
    __syncthreads();
    CLUSTER_SYNC();

    const int M = lens[NB - 1];
    const int grow0 = ((r0 >> 5) << 8) + cta * 32 + (r0 & 31);
    const int grow1 = ((r1 >> 5) << 8) + cta * 32 + (r1 & 31);
    const float* bihp = dir ? bih_b : bih_f;
    const float* bhhp = dir ? bhh_b : bhh_f;
    const float bx0 = bihp[grow0], bx1 = bihp[grow1];
    const float bh0 = bhhp[grow0], bh1 = bhhp[grow1];
    const float* w0p = w_s + r0 * KPAD;
    const float* w1p = w_s + r1 * KPAD;
    const float* a0p = embs + nb0 * 128;

    // peer addresses (tid0 only uses, cheap for all)
    unsigned dstXh[NCTA], mbFp[NCTA], mbEp[NCTA];
#pragma unroll
    for (int p = 0; p < NCTA; p++) {
        dstXh[p] = mapa_sm(base + OFF_XH, p) + cta * 4096;
        mbFp[p]  = mapa_sm(mbF_l, p);
        mbEp[p]  = mapa_sm(mbE_l, p);
    }

    // initial embedding gather (step 0): embs[nb][k] swizzled
    {
        int t0 = dir ? (M - 1) : 0;
        for (int i = tid; i < 1024; i += NTH) {
            int nb = i & 31, k4 = i >> 5;
            int tok = x[obs[nb] * TT + t0];
            float4 v = *(const float4*)(emb + (size_t)tok * EE + k4 * 4);
            int kx = (4 * k4) ^ (4 * ((nb >> 2) & 7));
            *(float4*)(embs + nb * 128 + kx) = v;
        }
    }
    __syncthreads();

    unsigned pf = 0, pe = 0;

    for (int s = 0; s < M; s++) {
        // ---- A: input projection k=0..127, k-pair f32x2, no packs ----
        {
            u64 ax[8];
#pragma unroll
            for (int j = 0; j < 4; j++) { ax[j] = pack2(bx0, 0.0f); ax[4 + j] = pack2(bx1, 0.0f); }
#pragma unroll 4
            for (int kq = 0; kq < 32; kq++) {
                int kx = (4 * kq) ^ sw;
                ulonglong2 w0 = *(const ulonglong2*)(w0p + 4 * kq);
                ulonglong2 w1 = *(const ulonglong2*)(w1p + 4 * kq);
                ulonglong2 a0 = *(const ulonglong2*)(a0p + kx);
                ulonglong2 a1 = *(const ulonglong2*)(a0p + 128 + kx);
                ulonglong2 a2 = *(const ulonglong2*)(a0p + 256 + kx);
                ulonglong2 a3 = *(const ulonglong2*)(a0p + 384 + kx);
                ax[0] = ffma2(w0.x, a0.x, ax[0]); ax[0] = ffma2(w0.y, a0.y, ax[0]);
                ax[1] = ffma2(w0.x, a1.x, ax[1]); ax[1] = ffma2(w0.y, a1.y, ax[1]);
                ax[2] = ffma2(w0.x, a2.x, ax[2]); ax[2] = ffma2(w0.y, a2.y, ax[2]);
                ax[3] = ffma2(w0.x, a3.x, ax[3]); ax[3] = ffma2(w0.y, a3.y, ax[3]);
                ax[4] = ffma2(w1.x, a0.x, ax[4]); ax[4] = ffma2(w1.y, a0.y, ax[4]);
                ax[5] = ffma2(w1.x, a1.x, ax[5]); ax[5] = ffma2(w1.y, a1.y, ax[5]);
                ax[6] = ffma2(w1.x, a2.x, ax[6]); ax[6] = ffma2(w1.y, a2.y, ax[6]);
                ax[7] = ffma2(w1.x, a3.x, ax[7]); ax[7] = ffma2(w1.y, a3.y, ax[7]);
            }
#pragma unroll
            for (int j = 0; j < 4; j++) {
                float lo, hi;
                unpack2(ax[j], lo, hi);     preX[r0 * PXP + nb0 + j] = lo + hi;
                unpack2(ax[4 + j], lo, hi); preX[r1 * PXP + nb0 + j] = lo + hi;
            }
        }

        // ---- wait for h^s; re-arm for h^{s+1} ----
        if (s > 0) {
            mbar_wait_par(mbF_l, pf);
            pf ^= 1;
            if (tid == 0 && s + 1 < M) mbar_arrive_expect_tx(mbF_l, XH_BYTES);
        }

        // ---- D: hidden projection k=128..383 over xh slices ----
        {
            u64 ah[8];
#pragma unroll
            for (int j = 0; j < 4; j++) { ah[j] = pack2(bh0, 0.0f); ah[4 + j] = pack2(bh1, 0.0f); }
#pragma unroll
            for (int sl = 0; sl < 8; sl++) {
                const float* xb = xh + sl * 1024 + nb0 * 32;
                const float* wk0 = w0p + 128 + 32 * sl;
                const float* wk1 = w1p + 128 + 32 * sl;
#pragma unroll
                for (int cq = 0; cq < 8; cq++) {
                    int kx = (4 * cq) ^ sw;
                    ulonglong2 w0 = *(const ulonglong2*)(wk0 + 4 * cq);
                    ulonglong2 w1 = *(const ulonglong2*)(wk1 + 4 * cq);
                    ulonglong2 a0 = *(const ulonglong2*)(xb + kx);
                    ulonglong2 a1 = *(const ulonglong2*)(xb + 32 + kx);
                    ulonglong2 a2 = *(const ulonglong2*)(xb + 64 + kx);
                    ulonglong2 a3 = *(const ulonglong2*)(xb + 96 + kx);
                    ah[0] = ffma2(w0.x, a0.x, ah[0]); ah[0] = ffma2(w0.y, a0.y, ah[0]);
                    ah[1] = ffma2(w0.x, a1.x, ah[1]); ah[1] = ffma2(w0.y, a1.y, ah[1]);
                    ah[2] = ffma2(w0.x, a2.x, ah[2]); ah[2] = ffma2(w0.y, a2.y, ah[2]);
                    ah[3] = ffma2(w0.x, a3.x, ah[3]); ah[3] = ffma2(w0.y, a3.y, ah[3]);
                    ah[4] = ffma2(w1.x, a0.x, ah[4]); ah[4] = ffma2(w1.y, a0.y, ah[4]);
                    ah[5] = ffma2(w1.x, a1.x, ah[5]); ah[5] = ffma2(w1.y, a1.y, ah[5]);
                    ah[6] = ffma2(w1.x, a2.x, ah[6]); ah[6] = ffma2(w1.y, a2.y, ah[6]);
                    ah[7] = ffma2(w1.x, a3.x, ah[7]); ah[7] = ffma2(w1.y, a3.y, ah[7]);
                }
            }
#pragma unroll
            for (int j = 0; j < 4; j++) {
                float lo, hi;
                unpack2(ah[j], lo, hi);     preH[r0 * PXP + nb0 + j] = lo + hi;
                unpack2(ah[4 + j], lo, hi); preH[r1 * PXP + nb0 + j] = lo + hi;
            }
        }
        __syncthreads();   // xh reads + pre stores complete

        // signal "done reading h^s" to every CTA
        if (tid == 0 && s + 1 < M) {
#pragma unroll
            for (int p = 0; p < NCTA; p++) mbar_arrive_remote(mbEp[p]);
        }

        // ---- E: gates + combine -> hstage  |  warps 8-11: prefetch next embedding ----
        if (tid < 256) {
            const int ec = tid >> 3;         // col 0..31
            const int e8 = tid & 7;
            const int swE = 4 * e8;
            const int tcur = dir ? (M - 1 - s) : s;
            float* hst = hstage + (s & 1) * 1024;
#pragma unroll
            for (int j = 0; j < 4; j++) {
                int nb = 4 * e8 + j;
                float xr = preX[ec * PXP + nb],        hr = preH[ec * PXP + nb];
                float xz = preX[(32 + ec) * PXP + nb], hz = preH[(32 + ec) * PXP + nb];
                float xn = preX[(64 + ec) * PXP + nb], hn = preH[(64 + ec) * PXP + nb];
                float hold = xh[cta * 1024 + nb * 32 + (ec ^ swE)];
                float r  = sigf(xr + hr);
                float z  = sigf(xz + hz);
                float nv = tanhfast(xn + r * hn);
                float hnew = (tcur < lens[nb]) ? ((1.0f - z) * nv + z * hold) : hold;
                if (s + 1 < M) hst[nb * 32 + (ec ^ swE)] = hnew;
                else g_h[(size_t)obs[nb] * (2 * HH) + dir * HH + cta * 32 + ec] = hnew;
            }
        } else if (s + 1 < M) {
            int tn = dir ? (M - 2 - s) : (s + 1);
            for (int i = tid - 256; i < 1024; i += 128) {
                int nb = i & 31, k4 = i >> 5;
                int tok = x[obs[nb] * TT + tn];
                float4 v = *(const float4*)(emb + (size_t)tok * EE + k4 * 4);
                int kx = (4 * k4) ^ (4 * ((nb >> 2) & 7));
                *(float4*)(embs + nb * 128 + kx) = v;
            }
        }
        __syncthreads();

        // ---- publish h^{s+1}: one bulk copy per peer ----
        if (s + 1 < M) {
            if (tid == 0) {
                mbar_wait_par(mbE_l, pe);   // everyone done reading h^s
                asm volatile("fence.proxy.async.shared::cta;" ::: "memory");
                unsigned src = base + OFF_HST + (unsigned)((s & 1) * 4096);
#pragma unroll
                for (int p = 0; p < NCTA; p++)
                    bulk_dsmem(dstXh[p], src, 4096, mbFp[p]);
            }
            pe ^= 1;
        }
    }

    CLUSTER_SYNC();
}

// ---------------- head: fc1 + relu + fc2 + L2 normalize ----------------
__global__ __launch_bounds__(128) void head_kernel(const float* __restrict__ fc1_b,
                                                   const float* __restrict__ fc2_b,
                                                   float* __restrict__ out) {
    __shared__ float hsm[512];
    __shared__ float hid[128];
    __shared__ float osm[64];
    __shared__ float inv_s;
    const int b = blockIdx.x, t = threadIdx.x;

    ((float4*)hsm)[t] = ((const float4*)(g_h + (size_t)b * 512))[t];
    __syncthreads();

    float acc = fc1_b[t];
#pragma unroll 8
    for (int k = 0; k < 512; k++) acc += g_fc1T[k * 128 + t] * hsm[k];
    hid[t] = fmaxf(acc, 0.0f);
    __syncthreads();

    if (t < 64) {
        float a = fc2_b[t];
#pragma unroll 8
        for (int k = 0; k < 128; k++) a += g_fc2T[k * 64 + t] * hid[k];
        osm[t] = a;
    }
    __syncthreads();
    if (t == 0) {
        float ss = 0.0f;
        for (int o = 0; o < 64; o++) ss += osm[o] * osm[o];
        inv_s = 1.0f / fmaxf(sqrtf(ss), 1e-12f);
    }
    __syncthreads();
    if (t < 64) out[b * 64 + t] = osm[t] * inv_s;
}

// ---------------- launch ----------------
extern "C" void kernel_launch(void* const* d_in, const int* in_sizes, int n_in,
                              void* d_out, int out_size) {
    const int*   x        = (const int*)d_in[0];
    const int*   lengths  = (const int*)d_in[1];
    const float* emb      = (const float*)d_in[2];
    const float* w_ih_f   = (const float*)d_in[3];
    const float* w_hh_f   = (const float*)d_in[4];
    const float* b_ih_f   = (const float*)d_in[5];
    const float* b_hh_f   = (const float*)d_in[6];
    const float* w_ih_b   = (const float*)d_in[7];
    const float* w_hh_b   = (const float*)d_in[8];
    const float* b_ih_b   = (const float*)d_in[9];
    const float* b_hh_b   = (const float*)d_in[10];
    const float* fc1_w    = (const float*)d_in[11];
    const float* fc1_b    = (const float*)d_in[12];
    const float* fc2_w    = (const float*)d_in[13];
    const float* fc2_b    = (const float*)d_in[14];
    float* out = (float*)d_out;

    static bool attr_set = false;
    if (!attr_set) {
        cudaFuncSetAttribute(gru_kernel, cudaFuncAttributeMaxDynamicSharedMemorySize, SMEM_SZ);
        attr_set = true;
    }

    const int total = 2 * NCTA * ROWS * KPAD + 512 * 128 + 128 * 64;
    prep_kernel<<<(total + 255) / 256, 256>>>(w_ih_f, w_hh_f, w_ih_b, w_hh_b, fc1_w, fc2_w);
    sort_kernel<<<1, BQ>>>(lengths);
    sort_kernel<<<1, BQ>>>(lengths);   // dummy: keeps gru at the ncu-captured slot
    dim3 gg(NCTA, NGRP, 2);
    gru_kernel<<<gg, NTH, SMEM_SZ>>>(x, lengths, emb, b_ih_f, b_hh_f, b_ih_b, b_hh_b);
    head_kernel<<<BQ, 128>>>(fc1_b, fc2_b, out);
}

// round 12
// speedup vs baseline: 3.3518x; 1.3820x over previous
#include <cuda_runtime.h>
#include <cuda_bf16.h>

#define BQ   256
#define TT   512
#define EE   128
#define HH   256
#define NB   8       // batches per group
#define NGRP 32      // groups per direction
#define NTH  384     // threads = gate rows per CTA
#define PXP  12      // preact pitch (floats)

typedef unsigned long long u64;

// ---------------- device scratch ----------------
__device__ float g_w[2 * 2 * 96 * 384 * 4];   // [dir][cta][kb][row][4]
__device__ float g_fc1T[512 * 128];
__device__ float g_fc2T[128 * 64];
__device__ float g_h[BQ * 2 * HH];
__device__ int   g_order[BQ];

// ---------------- math helpers ----------------
__device__ __forceinline__ u64 ffma2(u64 a, u64 b, u64 c) {
    u64 d; asm("fma.rn.f32x2 %0, %1, %2, %3;" : "=l"(d) : "l"(a), "l"(b), "l"(c)); return d;
}
__device__ __forceinline__ u64 pack2(float lo, float hi) {
    u64 d; asm("mov.b64 %0, {%1, %2};" : "=l"(d) : "f"(lo), "f"(hi)); return d;
}
__device__ __forceinline__ float sigf(float x) { return __fdividef(1.0f, 1.0f + __expf(-x)); }
__device__ __forceinline__ float tanhfast(float x) { return 1.0f - __fdividef(2.0f, __expf(2.0f * x) + 1.0f); }

// ---------------- cluster / mbarrier helpers (proven in R9/R10) ----------------
__device__ __forceinline__ unsigned smem_u32(const void* p) {
    unsigned a;
    asm("{ .reg .u64 t; cvta.to.shared.u64 t, %1; cvt.u32.u64 %0, t; }" : "=r"(a) : "l"(p));
    return a;
}
__device__ __forceinline__ unsigned mapa_sm(unsigned addr, unsigned rank) {
    unsigned r; asm("mapa.shared::cluster.u32 %0, %1, %2;" : "=r"(r) : "r"(addr), "r"(rank));
    return r;
}
__device__ __forceinline__ void mbar_init(unsigned a, unsigned c) {
    asm volatile("mbarrier.init.shared.b64 [%0], %1;" :: "r"(a), "r"(c) : "memory");
}
__device__ __forceinline__ void mbar_arrive_expect_tx(unsigned a, unsigned tx) {
    asm volatile("mbarrier.arrive.expect_tx.shared.b64 _, [%0], %1;" :: "r"(a), "r"(tx) : "memory");
}
__device__ __forceinline__ void mbar_wait_par(unsigned addr, unsigned par) {
    asm volatile(
        "{\n\t.reg .pred P;\n\t"
        "WAITLOOP_%=:\n\t"
        "mbarrier.try_wait.parity.acquire.cluster.shared::cta.b64 P, [%0], %1, 0x989680;\n\t"
        "@P bra.uni WAITDONE_%=;\n\t"
        "bra.uni WAITLOOP_%=;\n\t"
        "WAITDONE_%=:\n\t}"
        :: "r"(addr), "r"(par) : "memory");
}
__device__ __forceinline__ void bulk_dsmem(unsigned dst, unsigned src, unsigned bytes, unsigned mbar) {
    asm volatile("cp.async.bulk.shared::cluster.shared::cta.mbarrier::complete_tx::bytes [%0], [%1], %2, [%3];"
                 :: "r"(dst), "r"(src), "r"(bytes), "r"(mbar) : "memory");
}
#define CLUSTER_SYNC() do { \
    asm volatile("barrier.cluster.arrive.aligned;" ::: "memory"); \
    asm volatile("barrier.cluster.wait.aligned;"   ::: "memory"); \
} while (0)

// SMEM layout (bytes)
#define OFF_ES   0          // es[2][128][8] f32  : 8192
#define OFF_XH   8192       // xh[2][256][8] f32  : 16384
#define OFF_PX   24576      // preX[384][12] f32  : 18432
#define OFF_PH   43008      // preH[384][12] f32  : 18432
#define OFF_OB   61440      // int[8]
#define OFF_LEN  61472      // int[8]
#define OFF_MBF  61504      // u64 (16B pad)
#define SMEM_SZ  61568

// ---------------- prep: pack weights [dir][cta][kb][row][4] + fc transposes ----------------
__global__ void prep_kernel(const float* __restrict__ wihf, const float* __restrict__ whhf,
                            const float* __restrict__ wihb, const float* __restrict__ whhb,
                            const float* __restrict__ fc1w, const float* __restrict__ fc2w) {
    int idx = blockIdx.x * blockDim.x + threadIdx.x;
    const int NW = 2 * 2 * 96 * 384 * 4;             // 589824
    const int B1 = NW, B2 = B1 + 512 * 128, B3 = B2 + 128 * 64;
    if (idx < NW) {
        int j   = idx & 3;
        int row = (idx >> 2) % 384;
        int kb  = (idx / 1536) % 96;
        int cta = (idx / (1536 * 96)) % 2;
        int dir = idx / (1536 * 96 * 2);
        const float* wih = dir ? wihb : wihf;
        const float* whh = dir ? whhb : whhf;
        int k = 4 * kb + j;
        int grow = (row >> 7) * 256 + cta * 128 + (row & 127);   // gate*256 + global col
        g_w[idx] = (k < 128) ? wih[grow * EE + k] : whh[grow * HH + (k - 128)];
    } else if (idx < B2) {
        int o = idx - B1; int k = o / 128, i = o % 128;
        g_fc1T[o] = fc1w[i * 512 + k];
    } else if (idx < B3) {
        int o = idx - B2; int k = o / 64, i = o % 64;
        g_fc2T[o] = fc2w[i * 128 + k];
    }
}

// ---------------- sort batch by length (ascending bitonic) ----------------
__global__ void sort_kernel(const int* __restrict__ lengths) {
    __shared__ int key[BQ], val[BQ];
    unsigned t = threadIdx.x;
    key[t] = lengths[t]; val[t] = (int)t;
    __syncthreads();
    for (unsigned size = 2; size <= BQ; size <<= 1) {
        for (unsigned stride = size >> 1; stride > 0; stride >>= 1) {
            __syncthreads();
            unsigned j = t ^ stride;
            if (j > t) {
                bool up = ((t & size) == 0);
                int kt = key[t], kj = key[j];
                if ((kt > kj) == up) {
                    key[t] = kj; key[j] = kt;
                    int vt = val[t]; val[t] = val[j]; val[j] = vt;
                }
            }
        }
    }
    __syncthreads();
    g_order[t] = val[t];
}

// ---------------- GRU: 2-CTA cluster per (dir, group of 8), col-split ----------------
__global__ __launch_bounds__(NTH, 1) __cluster_dims__(2, 1, 1)
void gru_kernel(const int* __restrict__ x, const int* __restrict__ lengths,
                const float* __restrict__ emb,
                const float* __restrict__ bih_f, const float* __restrict__ bhh_f,
                const float* __restrict__ bih_b, const float* __restrict__ bhh_b) {

    const int cta = blockIdx.x;          // 0/1 : col half
    const int grp = blockIdx.y, dir = blockIdx.z;
    const int tid = threadIdx.x;         // = local gate row 0..383

    extern __shared__ __align__(16) char sm[];
    float* es   = (float*)(sm + OFF_ES);     // [2][128][8]
    float* xh   = (float*)(sm + OFF_XH);     // [2][256][8]
    float* preX = (float*)(sm + OFF_PX);     // [384][12]
    float* preH = (float*)(sm + OFF_PH);
    int*   obs  = (int*)(sm + OFF_OB);
    int*   lens = (int*)(sm + OFF_LEN);

    const unsigned base  = smem_u32(sm);
    const unsigned mbF_l = base + OFF_MBF;

    if (tid < NB) {
        int o = g_order[grp * NB + tid];
        obs[tid] = o;
        lens[tid] = lengths[o];
    }
    for (int i = tid; i < 2 * 256 * 8; i += NTH) xh[i] = 0.0f;
    if (tid == 0) mbar_init(mbF_l, 1);
    __syncthreads();
    if (tid == 0) mbar_arrive_expect_tx(mbF_l, 4096);   // arm phase 0 (receives h^1)
    __syncthreads();
    CLUSTER_SYNC();   // barrier + zeros visible before any peer bulk copy

    const int M = lens[NB - 1];
    const int grow = (tid >> 7) * 256 + cta * 128 + (tid & 127);
    const float* bihp = dir ? bih_b : bih_f;
    const float* bhhp = dir ? bhh_b : bhh_f;
    const float bx = bihp[grow];
    const float bh = bhhp[grow];
    const float* wg = g_w + (size_t)(dir * 2 + cta) * 96 * 1536;
    const unsigned peerXh  = mapa_sm(base + OFF_XH, cta ^ 1);
    const unsigned peerMbF = mapa_sm(mbF_l, cta ^ 1);

    // gather embedding for step 0 into es[0]
    if (tid < 256) {
        int t0 = dir ? (M - 1) : 0;
        int nb = tid & 7, k4 = tid >> 3;           // k4 0..31
        int tok = x[obs[nb] * TT + t0];
        float4 v = *(const float4*)(emb + (size_t)tok * EE + k4 * 4);
        float* e = es;
        e[(4 * k4 + 0) * 8 + nb] = v.x;
        e[(4 * k4 + 1) * 8 + nb] = v.y;
        e[(4 * k4 + 2) * 8 + nb] = v.z;
        e[(4 * k4 + 3) * 8 + nb] = v.w;
    }
    __syncthreads();

    for (int s = 0; s < M; s++) {
        const int par = s & 1;

        // ---- A: input projection k=0..127 (independent of peer -> hides skew) ----
        {
            u64 a0 = pack2(bx, bx), a1 = a0, a2 = a0, a3 = a0;
            const float* ep = es + par * 1024;
#pragma unroll 4
            for (int kb = 0; kb < 32; kb++) {
                float4 w4 = *(const float4*)(wg + kb * 1536 + tid * 4);
                const float* wj = (const float*)&w4;
#pragma unroll
                for (int j = 0; j < 4; j++) {
                    u64 wd = pack2(wj[j], wj[j]);
                    const float* ak = ep + (4 * kb + j) * 8;
                    ulonglong2 av = *(const ulonglong2*)ak;
                    ulonglong2 bv = *(const ulonglong2*)(ak + 4);
                    a0 = ffma2(wd, av.x, a0); a1 = ffma2(wd, av.y, a1);
                    a2 = ffma2(wd, bv.x, a2); a3 = ffma2(wd, bv.y, a3);
                }
            }
            *(ulonglong2*)(preX + tid * PXP)     = make_ulonglong2(a0, a1);
            *(ulonglong2*)(preX + tid * PXP + 4) = make_ulonglong2(a2, a3);
        }

        // ---- gather next embedding into es[par^1] (no peer dependence) ----
        if (s + 1 < M && tid < 256) {
            int tn = dir ? (M - 2 - s) : (s + 1);
            int nb = tid & 7, k4 = tid >> 3;
            int tok = x[obs[nb] * TT + tn];
            float4 v = *(const float4*)(emb + (size_t)tok * EE + k4 * 4);
            float* e = es + (par ^ 1) * 1024;
            e[(4 * k4 + 0) * 8 + nb] = v.x;
            e[(4 * k4 + 1) * 8 + nb] = v.y;
            e[(4 * k4 + 2) * 8 + nb] = v.z;
            e[(4 * k4 + 3) * 8 + nb] = v.w;
        }

        // ---- wait for peer's half of h^s; re-arm for h^{s+1} ----
        if (s > 0) {
            mbar_wait_par(mbF_l, (s - 1) & 1);
            if (tid == 0 && s + 1 < M) mbar_arrive_expect_tx(mbF_l, 4096);
        }

        // ---- D: hidden projection k=128..383 over full h^s ----
        {
            u64 h0 = pack2(bh, bh), h1 = h0, h2 = h0, h3 = h0;
            const float* xp = xh + par * 2048;
#pragma unroll 4
            for (int kb = 32; kb < 96; kb++) {
                float4 w4 = *(const float4*)(wg + kb * 1536 + tid * 4);
                const float* wj = (const float*)&w4;
#pragma unroll
                for (int j = 0; j < 4; j++) {
                    u64 wd = pack2(wj[j], wj[j]);
                    const float* ak = xp + (4 * kb + j - 128) * 8;
                    ulonglong2 av = *(const ulonglong2*)ak;
                    ulonglong2 bv = *(const ulonglong2*)(ak + 4);
                    h0 = ffma2(wd, av.x, h0); h1 = ffma2(wd, av.y, h1);
                    h2 = ffma2(wd, bv.x, h2); h3 = ffma2(wd, bv.y, h3);
                }
            }
            *(ulonglong2*)(preH + tid * PXP)     = make_ulonglong2(h0, h1);
            *(ulonglong2*)(preH + tid * PXP + 4) = make_ulonglong2(h2, h3);
        }
        __syncthreads();

        // ---- E: gates + combine; write own 128-col half of h^{s+1} ----
        {
            const int tcur = dir ? (M - 1 - s) : s;
            float* xw = xh + (par ^ 1) * 2048;
            const float* xr_ = xh + par * 2048;
            for (int i = tid; i < 1024; i += NTH) {
                int col = i >> 3, nb = i & 7;
                int cg = cta * 128 + col;
                float xr = preX[col * PXP + nb],         hr = preH[col * PXP + nb];
                float xz = preX[(128 + col) * PXP + nb], hz = preH[(128 + col) * PXP + nb];
                float xn = preX[(256 + col) * PXP + nb], hn = preH[(256 + col) * PXP + nb];
                float hold = xr_[cg * 8 + nb];
                float r  = sigf(xr + hr);
                float z  = sigf(xz + hz);
                float nv = tanhfast(xn + r * hn);
                float hnew = (tcur < lens[nb]) ? ((1.0f - z) * nv + z * hold) : hold;
                if (s + 1 < M) xw[cg * 8 + nb] = hnew;
                else g_h[(size_t)obs[nb] * (2 * HH) + dir * HH + cg] = hnew;
            }
        }
        __syncthreads();

        // ---- ship own half to peer (one 4KB bulk copy) ----
        if (s + 1 < M && tid == 0) {
            asm volatile("fence.proxy.async.shared::cta;" ::: "memory");
            unsigned off = (unsigned)(((par ^ 1) * 2048 + cta * 1024) * 4);
            bulk_dsmem(peerXh + off, base + OFF_XH + off, 4096, peerMbF);
        }
    }

    CLUSTER_SYNC();   // no CTA exits while peer's bulk copy may target it
}

// ---------------- head: fc1 + relu + fc2 + L2 normalize ----------------
__global__ __launch_bounds__(128) void head_kernel(const float* __restrict__ fc1_b,
                                                   const float* __restrict__ fc2_b,
                                                   float* __restrict__ out) {
    __shared__ float hsm[512];
    __shared__ float hid[128];
    __shared__ float osm[64];
    __shared__ float inv_s;
    const int b = blockIdx.x, t = threadIdx.x;

    ((float4*)hsm)[t] = ((const float4*)(g_h + (size_t)b * 512))[t];
    __syncthreads();

    float acc = fc1_b[t];
#pragma unroll 8
    for (int k = 0; k < 512; k++) acc += g_fc1T[k * 128 + t] * hsm[k];
    hid[t] = fmaxf(acc, 0.0f);
    __syncthreads();

    if (t < 64) {
        float a = fc2_b[t];
#pragma unroll 8
        for (int k = 0; k < 128; k++) a += g_fc2T[k * 64 + t] * hid[k];
        osm[t] = a;
    }
    __syncthreads();
    if (t == 0) {
        float ss = 0.0f;
        for (int o = 0; o < 64; o++) ss += osm[o] * osm[o];
        inv_s = 1.0f / fmaxf(sqrtf(ss), 1e-12f);
    }
    __syncthreads();
    if (t < 64) out[b * 64 + t] = osm[t] * inv_s;
}

// ---------------- launch ----------------
extern "C" void kernel_launch(void* const* d_in, const int* in_sizes, int n_in,
                              void* d_out, int out_size) {
    const int*   x        = (const int*)d_in[0];
    const int*   lengths  = (const int*)d_in[1];
    const float* emb      = (const float*)d_in[2];
    const float* w_ih_f   = (const float*)d_in[3];
    const float* w_hh_f   = (const float*)d_in[4];
    const float* b_ih_f   = (const float*)d_in[5];
    const float* b_hh_f   = (const float*)d_in[6];
    const float* w_ih_b   = (const float*)d_in[7];
    const float* w_hh_b   = (const float*)d_in[8];
    const float* b_ih_b   = (const float*)d_in[9];
    const float* b_hh_b   = (const float*)d_in[10];
    const float* fc1_w    = (const float*)d_in[11];
    const float* fc1_b    = (const float*)d_in[12];
    const float* fc2_w    = (const float*)d_in[13];
    const float* fc2_b    = (const float*)d_in[14];
    float* out = (float*)d_out;

    static bool attr_set = false;
    if (!attr_set) {
        cudaFuncSetAttribute(gru_kernel, cudaFuncAttributeMaxDynamicSharedMemorySize, SMEM_SZ);
        attr_set = true;
    }

    const int total = 2 * 2 * 96 * 384 * 4 + 512 * 128 + 128 * 64;
    prep_kernel<<<(total + 255) / 256, 256>>>(w_ih_f, w_hh_f, w_ih_b, w_hh_b, fc1_w, fc2_w);
    sort_kernel<<<1, BQ>>>(lengths);
    sort_kernel<<<1, BQ>>>(lengths);   // dummy: keeps gru at the ncu-captured launch slot
    dim3 gg(2, NGRP, 2);
    gru_kernel<<<gg, NTH, SMEM_SZ>>>(x, lengths, emb, b_ih_f, b_hh_f, b_ih_b, b_hh_b);
    head_kernel<<<BQ, 128>>>(fc1_b, fc2_b, out);
}

// round 13
// speedup vs baseline: 3.4010x; 1.0147x over previous
#include <cuda_runtime.h>
#include <cuda_bf16.h>

#define BQ   256
#define TT   512
#define EE   128
#define HH   256
#define NB   8       // batches per group
#define NGRP 32      // groups per direction
#define NTH  384     // threads = gate rows per CTA
#define PXP  12      // preact pitch (floats)
#define QC   27      // kb-blocks cached in SMEM (D-phase prefix kb 32..58)

typedef unsigned long long u64;

// ---------------- device scratch ----------------
__device__ float g_w[2 * 2 * 96 * 384 * 4];   // [dir][cta][kb][row][4]
__device__ float g_fc1T[512 * 128];
__device__ float g_fc2T[128 * 64];
__device__ float g_h[BQ * 2 * HH];
__device__ int   g_order[BQ];

// ---------------- math helpers ----------------
__device__ __forceinline__ u64 ffma2(u64 a, u64 b, u64 c) {
    u64 d; asm("fma.rn.f32x2 %0, %1, %2, %3;" : "=l"(d) : "l"(a), "l"(b), "l"(c)); return d;
}
__device__ __forceinline__ u64 pack2(float lo, float hi) {
    u64 d; asm("mov.b64 %0, {%1, %2};" : "=l"(d) : "f"(lo), "f"(hi)); return d;
}
__device__ __forceinline__ float sigf(float x) { return __fdividef(1.0f, 1.0f + __expf(-x)); }
__device__ __forceinline__ float tanhfast(float x) { return 1.0f - __fdividef(2.0f, __expf(2.0f * x) + 1.0f); }

// ---------------- cluster / mbarrier helpers (proven R9-R12) ----------------
__device__ __forceinline__ unsigned smem_u32(const void* p) {
    unsigned a;
    asm("{ .reg .u64 t; cvta.to.shared.u64 t, %1; cvt.u32.u64 %0, t; }" : "=r"(a) : "l"(p));
    return a;
}
__device__ __forceinline__ unsigned mapa_sm(unsigned addr, unsigned rank) {
    unsigned r; asm("mapa.shared::cluster.u32 %0, %1, %2;" : "=r"(r) : "r"(addr), "r"(rank));
    return r;
}
__device__ __forceinline__ void mbar_init(unsigned a, unsigned c) {
    asm volatile("mbarrier.init.shared.b64 [%0], %1;" :: "r"(a), "r"(c) : "memory");
}
__device__ __forceinline__ void mbar_arrive_expect_tx(unsigned a, unsigned tx) {
    asm volatile("mbarrier.arrive.expect_tx.shared.b64 _, [%0], %1;" :: "r"(a), "r"(tx) : "memory");
}
__device__ __forceinline__ void mbar_wait_par(unsigned addr, unsigned par) {
    asm volatile(
        "{\n\t.reg .pred P;\n\t"
        "WAITLOOP_%=:\n\t"
        "mbarrier.try_wait.parity.acquire.cluster.shared::cta.b64 P, [%0], %1, 0x989680;\n\t"
        "@P bra.uni WAITDONE_%=;\n\t"
        "bra.uni WAITLOOP_%=;\n\t"
        "WAITDONE_%=:\n\t}"
        :: "r"(addr), "r"(par) : "memory");
}
__device__ __forceinline__ void bulk_dsmem(unsigned dst, unsigned src, unsigned bytes, unsigned mbar) {
    asm volatile("cp.async.bulk.shared::cluster.shared::cta.mbarrier::complete_tx::bytes [%0], [%1], %2, [%3];"
                 :: "r"(dst), "r"(src), "r"(bytes), "r"(mbar) : "memory");
}
#define CLUSTER_SYNC() do { \
    asm volatile("barrier.cluster.arrive.aligned;" ::: "memory"); \
    asm volatile("barrier.cluster.wait.aligned;"   ::: "memory"); \
} while (0)

// SMEM layout (bytes)
#define OFF_ES   0          // es[2][128][8] f32  : 8192
#define OFF_XH   8192       // xh[2][256][8] f32  : 16384
#define OFF_PX   24576      // preX[384][12] f32  : 18432
#define OFF_PH   43008      // preH[384][12] f32  : 18432
#define OFF_OB   61440      // int[8]
#define OFF_LEN  61472      // int[8]
#define OFF_MBF  61504      // u64 (pad to 64)
#define OFF_WC   61568      // weight cache: QC*1536 f32 = 165888
#define SMEM_SZ  227456

// ---------------- prep: pack weights [dir][cta][kb][row][4] + fc transposes ----------------
__global__ void prep_kernel(const float* __restrict__ wihf, const float* __restrict__ whhf,
                            const float* __restrict__ wihb, const float* __restrict__ whhb,
                            const float* __restrict__ fc1w, const float* __restrict__ fc2w) {
    int idx = blockIdx.x * blockDim.x + threadIdx.x;
    const int NW = 2 * 2 * 96 * 384 * 4;             // 589824
    const int B1 = NW, B2 = B1 + 512 * 128, B3 = B2 + 128 * 64;
    if (idx < NW) {
        int j   = idx & 3;
        int row = (idx >> 2) % 384;
        int kb  = (idx / 1536) % 96;
        int cta = (idx / (1536 * 96)) % 2;
        int dir = idx / (1536 * 96 * 2);
        const float* wih = dir ? wihb : wihf;
        const float* whh = dir ? whhb : whhf;
        int k = 4 * kb + j;
        int grow = (row >> 7) * 256 + cta * 128 + (row & 127);   // gate*256 + global col
        g_w[idx] = (k < 128) ? wih[grow * EE + k] : whh[grow * HH + (k - 128)];
    } else if (idx < B2) {
        int o = idx - B1; int k = o / 128, i = o % 128;
        g_fc1T[o] = fc1w[i * 512 + k];
    } else if (idx < B3) {
        int o = idx - B2; int k = o / 64, i = o % 64;
        g_fc2T[o] = fc2w[i * 128 + k];
    }
}

// ---------------- sort batch by length (ascending bitonic) ----------------
__global__ void sort_kernel(const int* __restrict__ lengths) {
    __shared__ int key[BQ], val[BQ];
    unsigned t = threadIdx.x;
    key[t] = lengths[t]; val[t] = (int)t;
    __syncthreads();
    for (unsigned size = 2; size <= BQ; size <<= 1) {
        for (unsigned stride = size >> 1; stride > 0; stride >>= 1) {
            __syncthreads();
            unsigned j = t ^ stride;
            if (j > t) {
                bool up = ((t & size) == 0);
                int kt = key[t], kj = key[j];
                if ((kt > kj) == up) {
                    key[t] = kj; key[j] = kt;
                    int vt = val[t]; val[t] = val[j]; val[j] = vt;
                }
            }
        }
    }
    __syncthreads();
    g_order[t] = val[t];
}

// ---------------- GRU: 2-CTA cluster, col-split, SMEM weight cache + prefetch ----------------
__global__ __launch_bounds__(NTH, 1) __cluster_dims__(2, 1, 1)
void gru_kernel(const int* __restrict__ x, const int* __restrict__ lengths,
                const float* __restrict__ emb,
                const float* __restrict__ bih_f, const float* __restrict__ bhh_f,
                const float* __restrict__ bih_b, const float* __restrict__ bhh_b) {

    const int cta = blockIdx.x;          // 0/1 : col half
    const int grp = blockIdx.y, dir = blockIdx.z;
    const int tid = threadIdx.x;         // = local gate row 0..383

    extern __shared__ __align__(16) char sm[];
    float* es   = (float*)(sm + OFF_ES);     // [2][128][8]
    float* xh   = (float*)(sm + OFF_XH);     // [2][256][8]
    float* preX = (float*)(sm + OFF_PX);     // [384][12]
    float* preH = (float*)(sm + OFF_PH);
    float* wc   = (float*)(sm + OFF_WC);     // cached weight blocks kb 32..32+QC-1
    int*   obs  = (int*)(sm + OFF_OB);
    int*   lens = (int*)(sm + OFF_LEN);

    const unsigned base  = smem_u32(sm);
    const unsigned mbF_l = base + OFF_MBF;

    if (tid < NB) {
        int o = g_order[grp * NB + tid];
        obs[tid] = o;
        lens[tid] = lengths[o];
    }
    for (int i = tid; i < 2 * 256 * 8; i += NTH) xh[i] = 0.0f;
    if (tid == 0) mbar_init(mbF_l, 1);

    const float* wg = g_w + (size_t)(dir * 2 + cta) * 96 * 1536;

    // fill SMEM weight cache (one-time): blocks kb 32..32+QC-1
    {
        const float4* src = (const float4*)(wg + 32 * 1536);
        float4* dst = (float4*)wc;
        for (int i = tid; i < QC * 1536 / 4; i += NTH) dst[i] = src[i];
    }
    __syncthreads();
    if (tid == 0) mbar_arrive_expect_tx(mbF_l, 4096);   // arm phase 0 (receives h^1)
    __syncthreads();
    CLUSTER_SYNC();   // barrier + zeros visible before any peer bulk copy

    const int M = lens[NB - 1];
    const int grow = (tid >> 7) * 256 + cta * 128 + (tid & 127);
    const float* bihp = dir ? bih_b : bih_f;
    const float* bhhp = dir ? bhh_b : bhh_f;
    const float bx = bihp[grow];
    const float bh = bhhp[grow];
    const unsigned peerXh  = mapa_sm(base + OFF_XH, cta ^ 1);
    const unsigned peerMbF = mapa_sm(mbF_l, cta ^ 1);
    const float* wtp = wg + tid * 4;     // per-thread weight column base
    const float* wcp = wc + tid * 4;

    // gather embedding for step 0 into es[0]
    if (tid < 256) {
        int t0 = dir ? (M - 1) : 0;
        int nb = tid & 7, k4 = tid >> 3;
        int tok = x[obs[nb] * TT + t0];
        float4 v = *(const float4*)(emb + (size_t)tok * EE + k4 * 4);
        float* e = es;
        e[(4 * k4 + 0) * 8 + nb] = v.x;
        e[(4 * k4 + 1) * 8 + nb] = v.y;
        e[(4 * k4 + 2) * 8 + nb] = v.z;
        e[(4 * k4 + 3) * 8 + nb] = v.w;
    }
    __syncthreads();

    for (int s = 0; s < M; s++) {
        const int par = s & 1;

        // ---- A: input projection k=0..127, rolling 4-deep LDG prefetch ----
        {
            u64 a0 = pack2(bx, bx), a1 = a0, a2 = a0, a3 = a0;
            const float* ep = es + par * 1024;
            float4 wbuf[4];
#pragma unroll
            for (int i = 0; i < 4; i++) wbuf[i] = *(const float4*)(wtp + i * 1536);
#pragma unroll 8
            for (int kb = 0; kb < 32; kb++) {
                float4 w4 = wbuf[kb & 3];
                if (kb + 4 < 32) wbuf[kb & 3] = *(const float4*)(wtp + (kb + 4) * 1536);
                const float* wj = (const float*)&w4;
#pragma unroll
                for (int j = 0; j < 4; j++) {
                    u64 wd = pack2(wj[j], wj[j]);
                    const float* ak = ep + (4 * kb + j) * 8;
                    ulonglong2 av = *(const ulonglong2*)ak;
                    ulonglong2 bv = *(const ulonglong2*)(ak + 4);
                    a0 = ffma2(wd, av.x, a0); a1 = ffma2(wd, av.y, a1);
                    a2 = ffma2(wd, bv.x, a2); a3 = ffma2(wd, bv.y, a3);
                }
            }
            *(ulonglong2*)(preX + tid * PXP)     = make_ulonglong2(a0, a1);
            *(ulonglong2*)(preX + tid * PXP + 4) = make_ulonglong2(a2, a3);
        }

        // ---- gather next embedding into es[par^1] (no peer dependence) ----
        if (s + 1 < M && tid < 256) {
            int tn = dir ? (M - 2 - s) : (s + 1);
            int nb = tid & 7, k4 = tid >> 3;
            int tok = x[obs[nb] * TT + tn];
            float4 v = *(const float4*)(emb + (size_t)tok * EE + k4 * 4);
            float* e = es + (par ^ 1) * 1024;
            e[(4 * k4 + 0) * 8 + nb] = v.x;
            e[(4 * k4 + 1) * 8 + nb] = v.y;
            e[(4 * k4 + 2) * 8 + nb] = v.z;
            e[(4 * k4 + 3) * 8 + nb] = v.w;
        }

        // ---- prefetch first streamed D weight blocks (kb 32+QC..) BEFORE wait ----
        float4 wpf[4];
#pragma unroll
        for (int i = 0; i < 4; i++) wpf[i] = *(const float4*)(wtp + (32 + QC + i) * 1536);

        // ---- wait for peer's half of h^s; re-arm for h^{s+1} ----
        if (s > 0) {
            mbar_wait_par(mbF_l, (s - 1) & 1);
            if (tid == 0 && s + 1 < M) mbar_arrive_expect_tx(mbF_l, 4096);
        }

        // ---- D: hidden projection k=128..383 (cached prefix, then streamed) ----
        {
            u64 h0 = pack2(bh, bh), h1 = h0, h2 = h0, h3 = h0;
            const float* xp = xh + par * 2048;
            // cached blocks kb = 32 .. 32+QC-1 (LDS, zero LDG dependence)
#pragma unroll 8
            for (int kc = 0; kc < QC; kc++) {
                float4 w4 = *(const float4*)(wcp + kc * 1536);
                const float* wj = (const float*)&w4;
#pragma unroll
                for (int j = 0; j < 4; j++) {
                    u64 wd = pack2(wj[j], wj[j]);
                    const float* ak = xp + (4 * (32 + kc) + j - 128) * 8;
                    ulonglong2 av = *(const ulonglong2*)ak;
                    ulonglong2 bv = *(const ulonglong2*)(ak + 4);
                    h0 = ffma2(wd, av.x, h0); h1 = ffma2(wd, av.y, h1);
                    h2 = ffma2(wd, bv.x, h2); h3 = ffma2(wd, bv.y, h3);
                }
            }
            // streamed blocks kb = 32+QC .. 95 with rolling prefetch
#pragma unroll 8
            for (int kb = 32 + QC; kb < 96; kb++) {
                float4 w4 = wpf[(kb - 32 - QC) & 3];
                if (kb + 4 < 96) wpf[(kb - 32 - QC) & 3] = *(const float4*)(wtp + (kb + 4) * 1536);
                const float* wj = (const float*)&w4;
#pragma unroll
                for (int j = 0; j < 4; j++) {
                    u64 wd = pack2(wj[j], wj[j]);
                    const float* ak = xp + (4 * kb + j - 128) * 8;
                    ulonglong2 av = *(const ulonglong2*)ak;
                    ulonglong2 bv = *(const ulonglong2*)(ak + 4);
                    h0 = ffma2(wd, av.x, h0); h1 = ffma2(wd, av.y, h1);
                    h2 = ffma2(wd, bv.x, h2); h3 = ffma2(wd, bv.y, h3);
                }
            }
            *(ulonglong2*)(preH + tid * PXP)     = make_ulonglong2(h0, h1);
            *(ulonglong2*)(preH + tid * PXP + 4) = make_ulonglong2(h2, h3);
        }
        __syncthreads();

        // ---- E: gates + combine; write own 128-col half of h^{s+1} ----
        {
            const int tcur = dir ? (M - 1 - s) : s;
            float* xw = xh + (par ^ 1) * 2048;
            const float* xr_ = xh + par * 2048;
            for (int i = tid; i < 1024; i += NTH) {
                int col = i >> 3, nb = i & 7;
                int cg = cta * 128 + col;
                float xr = preX[col * PXP + nb],         hr = preH[col * PXP + nb];
                float xz = preX[(128 + col) * PXP + nb], hz = preH[(128 + col) * PXP + nb];
                float xn = preX[(256 + col) * PXP + nb], hn = preH[(256 + col) * PXP + nb];
                float hold = xr_[cg * 8 + nb];
                float r  = sigf(xr + hr);
                float z  = sigf(xz + hz);
                float nv = tanhfast(xn + r * hn);
                float hnew = (tcur < lens[nb]) ? ((1.0f - z) * nv + z * hold) : hold;
                if (s + 1 < M) xw[cg * 8 + nb] = hnew;
                else g_h[(size_t)obs[nb] * (2 * HH) + dir * HH + cg] = hnew;
            }
        }
        __syncthreads();

        // ---- ship own half to peer (one 4KB bulk copy) ----
        if (s + 1 < M && tid == 0) {
            asm volatile("fence.proxy.async.shared::cta;" ::: "memory");
            unsigned off = (unsigned)(((par ^ 1) * 2048 + cta * 1024) * 4);
            bulk_dsmem(peerXh + off, base + OFF_XH + off, 4096, peerMbF);
        }
    }

    CLUSTER_SYNC();   // no CTA exits while peer's bulk copy may target it
}

// ---------------- head: fc1 + relu + fc2 + L2 normalize ----------------
__global__ __launch_bounds__(128) void head_kernel(const float* __restrict__ fc1_b,
                                                   const float* __restrict__ fc2_b,
                                                   float* __restrict__ out) {
    __shared__ float hsm[512];
    __shared__ float hid[128];
    __shared__ float osm[64];
    __shared__ float inv_s;
    const int b = blockIdx.x, t = threadIdx.x;

    ((float4*)hsm)[t] = ((const float4*)(g_h + (size_t)b * 512))[t];
    __syncthreads();

    float acc = fc1_b[t];
#pragma unroll 8
    for (int k = 0; k < 512; k++) acc += g_fc1T[k * 128 + t] * hsm[k];
    hid[t] = fmaxf(acc, 0.0f);
    __syncthreads();

    if (t < 64) {
        float a = fc2_b[t];
#pragma unroll 8
        for (int k = 0; k < 128; k++) a += g_fc2T[k * 64 + t] * hid[k];
        osm[t] = a;
    }
    __syncthreads();
    if (t == 0) {
        float ss = 0.0f;
        for (int o = 0; o < 64; o++) ss += osm[o] * osm[o];
        inv_s = 1.0f / fmaxf(sqrtf(ss), 1e-12f);
    }
    __syncthreads();
    if (t < 64) out[b * 64 + t] = osm[t] * inv_s;
}

// ---------------- launch ----------------
extern "C" void kernel_launch(void* const* d_in, const int* in_sizes, int n_in,
                              void* d_out, int out_size) {
    const int*   x        = (const int*)d_in[0];
    const int*   lengths  = (const int*)d_in[1];
    const float* emb      = (const float*)d_in[2];
    const float* w_ih_f   = (const float*)d_in[3];
    const float* w_hh_f   = (const float*)d_in[4];
    const float* b_ih_f   = (const float*)d_in[5];
    const float* b_hh_f   = (const float*)d_in[6];
    const float* w_ih_b   = (const float*)d_in[7];
    const float* w_hh_b   = (const float*)d_in[8];
    const float* b_ih_b   = (const float*)d_in[9];
    const float* b_hh_b   = (const float*)d_in[10];
    const float* fc1_w    = (const float*)d_in[11];
    const float* fc1_b    = (const float*)d_in[12];
    const float* fc2_w    = (const float*)d_in[13];
    const float* fc2_b    = (const float*)d_in[14];
    float* out = (float*)d_out;

    static bool attr_set = false;
    if (!attr_set) {
        cudaFuncSetAttribute(gru_kernel, cudaFuncAttributeMaxDynamicSharedMemorySize, SMEM_SZ);
        attr_set = true;
    }

    const int total = 2 * 2 * 96 * 384 * 4 + 512 * 128 + 128 * 64;
    prep_kernel<<<(total + 255) / 256, 256>>>(w_ih_f, w_hh_f, w_ih_b, w_hh_b, fc1_w, fc2_w);
    sort_kernel<<<1, BQ>>>(lengths);
    sort_kernel<<<1, BQ>>>(lengths);   // dummy: keeps gru at the ncu-captured launch slot
    dim3 gg(2, NGRP, 2);
    gru_kernel<<<gg, NTH, SMEM_SZ>>>(x, lengths, emb, b_ih_f, b_hh_f, b_ih_b, b_hh_b);
    head_kernel<<<BQ, 128>>>(fc1_b, fc2_b, out);
}